// round 15
// baseline (speedup 1.0000x reference)
#include <cuda_runtime.h>
#include <math.h>

// Problem constants
#define B_TOT 256
#define NBLK  256
#define NTHR  320
#define AIN   8
#define MUL   1024
#define NK    20
#define NO    16

// Persistent scratch (device globals; allocation-free)
__device__ __align__(16) float g_c[NK * MUL];
__device__ __align__(16) float g_b[NK * MUL];
__device__ __align__(16) float g_bpart[16 * NK * MUL];     // [bs][k][m]
__device__ __align__(16) float g_xsp[16 * B_TOT * AIN];    // [mt][b][a]
__device__ __align__(16) float g_yh[16 * B_TOT * NK * AIN];// [mt][b][k][a]
__device__ unsigned g_cnt = 0;
__device__ unsigned g_rel = 0;

// Packed f32x2 FMA
#define FMA2(acc, a, b) \
    asm("fma.rn.f32x2 %0, %1, %2, %0;" : "+l"(acc) : "l"(a), "l"(b))

__device__ __forceinline__ float pair_sum(unsigned long long u) {
    float lo = __uint_as_float((unsigned)(u & 0xffffffffu));
    float hi = __uint_as_float((unsigned)(u >> 32));
    return lo + hi;
}

// Replay-safe grid barrier (all 256 blocks co-resident at 2/SM).
// Counter reset by last arriver BEFORE release bump -> g_cnt==0 at exit.
__device__ __forceinline__ void grid_barrier() {
    __threadfence();
    __syncthreads();
    if (threadIdx.x == 0) {
        unsigned r0;
        asm volatile("ld.acquire.gpu.u32 %0, [%1];" : "=r"(r0) : "l"(&g_rel));
        unsigned old = atomicAdd(&g_cnt, 1);
        if (old == NBLK - 1) {
            atomicExch(&g_cnt, 0);
            __threadfence();
            atomicAdd(&g_rel, 1);
        } else {
            unsigned r;
            do {
                __nanosleep(64);
                asm volatile("ld.acquire.gpu.u32 %0, [%1];" : "=r"(r) : "l"(&g_rel));
            } while (r == r0);
        }
        __threadfence();
    }
    __syncthreads();
}

// SMEM layout (floats): total 18688 = 74752 B; 2 blocks/SM = 149.5 KB
#define XS 0        // xs [16][512]      8192 (resident x tile, staged ONCE)
#define YS 8192     // ysm [16][160]     2560 (also csd u64 overlay in yp)
#define WV 10752    // wvs [16][160]     2560
#define SV 13312    // svm [16][320]     5120 (also esm overlay in softmax)
#define CQ 18432    // cqm [256]          256 (also xsum/red scratch)
#define SM_FLOATS 18688

// ---------------------------------------------------------------------------
// Tail + agree (shared by u0/u1): ysm[16][160] -> s -> squash -> v -> wv,
// then agree partials from the RESIDENT x tile -> g_bpart[bs][k][mt-range].
// ---------------------------------------------------------------------------
__device__ __forceinline__ void tail_and_agree(
    float* sm, const float* __restrict__ W, int mt, int bs, int tid)
{
    const int k = tid >> 4, o = tid & 15;

    // s = W y (thread = (k,o)), 16 batches
    {
        const float4* wp4 = (const float4*)(W + tid * 8);
        float4 wA = wp4[0], wB = wp4[1];
        #pragma unroll
        for (int bb = 0; bb < 16; bb++) {
            const float* y = sm + YS + bb * 160 + k * 8;
            float s = wA.x * y[0] + wA.y * y[1] + wA.z * y[2] + wA.w * y[3]
                    + wB.x * y[4] + wB.y * y[5] + wB.z * y[6] + wB.w * y[7];
            sm[SV + bb * 320 + tid] = s;
        }
    }
    __syncthreads();

    // squash coefficients (sum over classes, per reference)
    if (tid < 256) {
        int bb = tid >> 4, oo = tid & 15;
        float msq = 0.f;
        #pragma unroll
        for (int kk = 0; kk < NK; kk++) {
            float t = sm[SV + bb * 320 + kk * 16 + oo];
            msq += t * t;
        }
        sm[CQ + tid] = msq / ((1.f + msq) * sqrtf(msq));
    }
    __syncthreads();

    // v = coeff * s (in place)
    {
        #pragma unroll
        for (int bb = 0; bb < 16; bb++)
            sm[SV + bb * 320 + tid] *= sm[CQ + bb * 16 + o];
    }
    __syncthreads();

    // wv[b][k][a] = sum_o W[k,o,a] * v[b,k,o]
    {
        const int r   = tid % 160;
        const int bb0 = tid / 160;
        const int kk  = r >> 3, aa = r & 7;
        float w16[16];
        #pragma unroll
        for (int oo = 0; oo < 16; oo++) w16[oo] = W[(kk * 16 + oo) * 8 + aa];
        #pragma unroll
        for (int s8 = 0; s8 < 8; s8++) {
            int bb = bb0 + s8 * 2;
            float acc = 0.f;
            #pragma unroll
            for (int oo = 0; oo < 16; oo++)
                acc += w16[oo] * sm[SV + bb * 320 + kk * 16 + oo];
            sm[WV + bb * 160 + r] = acc;
        }
    }
    __syncthreads();

    // agree partials from RESIDENT xs tile
    const int mi4 = tid / NK;
    const int k2  = tid % NK;
    unsigned long long acc[4];
    #pragma unroll
    for (int i = 0; i < 4; i++) acc[i] = 0ull;

    #pragma unroll 4
    for (int bb = 0; bb < 16; bb++) {
        const ulonglong2* wp = (const ulonglong2*)(sm + WV + bb * 160 + k2 * 8);
        ulonglong2 wA = wp[0], wB = wp[1];
        const ulonglong2* xp = (const ulonglong2*)(sm + XS + bb * 512 + mi4 * 32);
        #pragma unroll
        for (int mm = 0; mm < 4; mm++) {
            ulonglong2 xA = xp[mm * 2];
            ulonglong2 xB = xp[mm * 2 + 1];
            FMA2(acc[mm], xA.x, wA.x);
            FMA2(acc[mm], xA.y, wA.y);
            FMA2(acc[mm], xB.x, wB.x);
            FMA2(acc[mm], xB.y, wB.y);
        }
    }

    float* dst = g_bpart + (size_t)bs * (NK * MUL) + k2 * MUL + mt * 64 + mi4 * 4;
    #pragma unroll
    for (int mm = 0; mm < 4; mm++) dst[mm] = pair_sum(acc[mm]) * (1.0f / 256.0f);
}

// ---------------------------------------------------------------------------
// yp phase: y-partials over this block's m-tile from the RESIDENT x tile.
// thread = (bl, k); flat loop, no shuffles. Writes g_yh[mt][b][k][a].
// ---------------------------------------------------------------------------
__device__ __forceinline__ void yp_phase(float* sm, int mt, int bbase, int tid)
{
    unsigned long long* csd = (unsigned long long*)(sm + YS);   // [64 m][20 k]
    for (int i = tid; i < 1280; i += NTHR) {
        int k = i >> 6, m = i & 63;
        unsigned u = __float_as_uint(g_c[k * MUL + mt * 64 + m]);
        csd[m * 20 + k] = (unsigned long long)u | ((unsigned long long)u << 32);
    }
    __syncthreads();

    const int bl = tid / 20, k = tid % 20;
    const float* xb = sm + XS + bl * 512;

    unsigned long long a0 = 0ull, a1 = 0ull, a2 = 0ull, a3 = 0ull;
    #pragma unroll 8
    for (int m = 0; m < 64; m++) {
        unsigned long long cv = csd[m * 20 + k];
        const ulonglong2* xp = (const ulonglong2*)(xb + m * 8);
        ulonglong2 xA = xp[0];
        ulonglong2 xB = xp[1];
        FMA2(a0, xA.x, cv); FMA2(a1, xA.y, cv);
        FMA2(a2, xB.x, cv); FMA2(a3, xB.y, cv);
    }
    unsigned long long* dst = (unsigned long long*)
        (g_yh + ((size_t)(mt * 256 + bbase + bl)) * 160 + k * 8);
    dst[0] = a0; dst[1] = a1; dst[2] = a2; dst[3] = a3;
    __syncthreads();
}

// ---------------------------------------------------------------------------
// Softmax phase: blocks with fid < 20 handle class k = fid.
// No max subtraction (inputs bounded, fp32-safe; validated R12).
// ---------------------------------------------------------------------------
__device__ __forceinline__ void softmax_phase(float* sm, int fid, int tid, int accum)
{
    if (fid < NK) {
        const int k = fid;
        float* esm = sm + SV;                 // [1024]
        const int lane = tid & 31, wp = tid >> 5;

        float lsum = 0.f;
        #pragma unroll
        for (int p = 0; p < 4; p++) {
            int m = tid + p * NTHR;
            if (m < MUL) {
                float b = accum ? g_b[k * MUL + m] : 0.f;
                #pragma unroll
                for (int bsx = 0; bsx < 16; bsx++)
                    b += g_bpart[(size_t)bsx * (NK * MUL) + k * MUL + m];
                g_b[k * MUL + m] = b;
                float e = expf(b);
                esm[m] = e;
                lsum += e;
            }
        }
        #pragma unroll
        for (int off = 16; off; off >>= 1)
            lsum += __shfl_xor_sync(0xffffffffu, lsum, off);
        if (lane == 0) sm[CQ + wp] = lsum;
        __syncthreads();
        if (tid == 0) {
            float ss = 0.f;
            #pragma unroll
            for (int i = 0; i < 10; i++) ss += sm[CQ + i];
            sm[CQ + 16] = 1.0f / ss;
        }
        __syncthreads();
        float inv = sm[CQ + 16];
        #pragma unroll
        for (int p = 0; p < 4; p++) {
            int m = tid + p * NTHR;
            if (m < MUL) g_c[k * MUL + m] = esm[m] * inv;
        }
        __syncthreads();
    }
}

// ---------------------------------------------------------------------------
// Single persistent kernel.
// ---------------------------------------------------------------------------
__global__ void __launch_bounds__(NTHR, 2)
cap_kernel(const float* __restrict__ x, const float* __restrict__ W,
           float* __restrict__ out)
{
    extern __shared__ float sm[];
    const int tid = threadIdx.x;
    const int mt  = blockIdx.x;
    const int bs  = blockIdx.y;
    const int fid = bs * 16 + mt;
    const int bbase = bs * 16;

    // ===== P0: stage resident x tile ONCE; xsum partials =====
    for (int i = tid; i < 2048; i += NTHR) {
        int bi = i >> 7, rr = i & 127;
        ((float4*)(sm + XS + bi * 512))[rr] =
            ((const float4*)(x + (size_t)(bbase + bi) * 8192 + mt * 512))[rr];
    }
    __syncthreads();
    if (tid < 128) {
        int bb = tid >> 3, a = tid & 7;
        float s = 0.f;
        #pragma unroll 16
        for (int m = 0; m < 64; m++) s += sm[XS + bb * 512 + m * 8 + a];
        g_xsp[mt * 2048 + (bbase + bb) * 8 + a] = s;
    }
    grid_barrier();

    // ===== P1: u0 (y0 from xsp, tail, wv, agree) =====
    if (tid < 128) {
        int bb = tid >> 3, a = tid & 7;
        float s = 0.f;
        #pragma unroll
        for (int mtt = 0; mtt < 16; mtt++)
            s += g_xsp[mtt * 2048 + (bbase + bb) * 8 + a];
        sm[CQ + tid] = s * (1.0f / 1024.0f);
    }
    __syncthreads();
    for (int i = tid; i < 2560; i += NTHR) {
        int bb = i / 160, r = i % 160;
        sm[YS + i] = sm[CQ + bb * 8 + (r & 7)];
    }
    __syncthreads();
    tail_and_agree(sm, W, mt, bs, tid);
    grid_barrier();

    // ===== P2: S0 -> c1 =====
    softmax_phase(sm, fid, tid, 0);
    grid_barrier();

    // ===== P3: yp1 =====
    yp_phase(sm, mt, bbase, tid);
    grid_barrier();

    // ===== P4: u1 (combine yh -> y, tail, wv, agree) =====
    for (int i = tid; i < 640; i += NTHR) {
        int bb = i / 40, r4 = i % 40;
        float4 f = make_float4(0.f, 0.f, 0.f, 0.f);
        #pragma unroll
        for (int mtt = 0; mtt < 16; mtt++) {
            float4 v = ((const float4*)(g_yh +
                        ((size_t)(mtt * 256 + bbase + bb)) * 160))[r4];
            f.x += v.x; f.y += v.y; f.z += v.z; f.w += v.w;
        }
        ((float4*)(sm + YS + bb * 160))[r4] = f;
    }
    __syncthreads();
    tail_and_agree(sm, W, mt, bs, tid);
    grid_barrier();

    // ===== P5: S1 -> c2 =====
    softmax_phase(sm, fid, tid, 1);
    grid_barrier();

    // ===== P6: yp2 =====
    yp_phase(sm, mt, bbase, tid);
    grid_barrier();

    // ===== P7: out (block fid = batch) =====
    {
        const int b = fid;
        if (tid < 160) {
            float f = 0.f;
            #pragma unroll
            for (int mtt = 0; mtt < 16; mtt++)
                f += g_yh[((size_t)(mtt * 256 + b)) * 160 + tid];
            sm[YS + tid] = f;
        }
        __syncthreads();

        const int k = tid >> 4, o = tid & 15;
        float s = 0.f;
        #pragma unroll
        for (int a = 0; a < 8; a++) s += W[tid * 8 + a] * sm[YS + k * 8 + a];
        sm[SV + tid] = s;
        __syncthreads();

        if (tid < NO) {
            float msq = 0.f;
            #pragma unroll
            for (int kk = 0; kk < NK; kk++) {
                float t = sm[SV + kk * NO + tid];
                msq += t * t;
            }
            sm[CQ + tid] = msq / ((1.f + msq) * sqrtf(msq));
        }
        __syncthreads();

        out[(size_t)b * 320 + tid] = sm[CQ + o] * s;
    }
}

// ---------------------------------------------------------------------------
extern "C" void kernel_launch(void* const* d_in, const int* in_sizes, int n_in,
                              void* d_out, int out_size)
{
    const float* x = (const float*)d_in[0];   // [256][1024][8] flat view
    const float* W = (const float*)d_in[1];   // [20][16][8]
    float* out = (float*)d_out;               // [256][20][16][1]

    const int SMEM = SM_FLOATS * (int)sizeof(float);   // 74752 B
    cudaFuncSetAttribute(cap_kernel,
                         cudaFuncAttributeMaxDynamicSharedMemorySize, SMEM);

    dim3 grid(16, 16);
    cap_kernel<<<grid, NTHR, SMEM>>>(x, W, out);
}

// round 16
// speedup vs baseline: 1.1727x; 1.1727x over previous
#include <cuda_runtime.h>
#include <math.h>

// Problem constants
#define B_TOT 256
#define AIN   8
#define MUL   1024
#define NK    20
#define NO    16
#define PLF   1036          // plane stride (floats)

// Persistent scratch (device globals; allocation-free)
__device__ __align__(16) float g_c[NK * MUL];
__device__ __align__(16) float g_b[NK * MUL];
__device__ __align__(16) float g_bpart[128 * NK * MUL];   // per-F-block agree slices

// Packed f32x2 FMA
#define FMA2(acc, a, b) \
    asm("fma.rn.f32x2 %0, %1, %2, %0;" : "+l"(acc) : "l"(a), "l"(b))

__device__ __forceinline__ float lo_f(unsigned long long u) {
    return __uint_as_float((unsigned)(u & 0xffffffffu));
}
__device__ __forceinline__ float hi_f(unsigned long long u) {
    return __uint_as_float((unsigned)(u >> 32));
}

#define WARP_RED_SUM(v)                                   \
  do {                                                    \
    v += __shfl_xor_sync(0xffffffffu, v, 16);             \
    v += __shfl_xor_sync(0xffffffffu, v, 8);              \
    v += __shfl_xor_sync(0xffffffffu, v, 4);              \
    v += __shfl_xor_sync(0xffffffffu, v, 2);              \
    v += __shfl_xor_sync(0xffffffffu, v, 1);              \
  } while (0)

// F smem layout (floats); total 38384 = 153.5 KB dynamic, 1 block/SM
#define XS   0          // x planes [16][PLF]        16576
#define CS   16576      // c [20][1024]; agr overlay [1024][20]  20480
#define YS   37056      // ysm [2][20][8]              320
#define SV   37376      // svm [2][320]                640
#define CQ   38016      // cqm [2][16]                  32
#define WVm  38048      // wvm [2][160]                320
#define RED  38368      // red [16]                     16
#define F_FLOATS 38384
#define F_THREADS 640

// ---------------------------------------------------------------------------
// Fused kernel: block = batch-pair (128 blocks).
//   stage x planes (+c if !uniform) -> y -> tail(s,squash,v) ->
//   final: write out | else: wv (smem) -> agree partials -> g_bpart[block].
// ---------------------------------------------------------------------------
__global__ void __launch_bounds__(F_THREADS, 1)
fused_kernel(const float* __restrict__ x, const float* __restrict__ W,
             float* __restrict__ out, int uniform_c, int final_iter)
{
    extern __shared__ float sm[];
    const int tid = threadIdx.x;
    const int b0  = blockIdx.x * 2;

    // ---- stage x transposed to planes ----
    {
        const float4* xsrc = (const float4*)(x + (size_t)b0 * 8192);
        #pragma unroll 2
        for (int i = tid; i < 4096; i += F_THREADS) {
            int bl = i >> 11, f = i & 2047;
            int m = f >> 1, half = f & 1;
            float4 v = xsrc[i];
            float* base = sm + XS + (bl * 8 + half * 4) * PLF + m;
            base[0 * PLF] = v.x; base[1 * PLF] = v.y;
            base[2 * PLF] = v.z; base[3 * PLF] = v.w;
        }
    }
    // ---- stage c (skipped on uniform iteration 0) ----
    if (!uniform_c) {
        const float4* csrc = (const float4*)g_c;
        float4* cdst = (float4*)(sm + CS);
        #pragma unroll
        for (int i = 0; i < 8; i++) cdst[tid + i * F_THREADS] = csrc[tid + i * F_THREADS];
    }
    __syncthreads();

    // ---- y phase ----
    if (uniform_c) {
        const int w = tid >> 5, lane = tid & 31;
        if (w < 16) {
            const float* pl = sm + XS + w * PLF;
            float s = 0.f;
            #pragma unroll 8
            for (int t = 0; t < 32; t++) s += pl[t * 32 + lane];
            WARP_RED_SUM(s);
            if (lane == 0) sm[RED + w] = s;
        }
        __syncthreads();
        if (tid < 320) {
            int bl = tid / 160, rr = tid % 160;
            sm[YS + bl * 160 + rr] = sm[RED + bl * 8 + (rr & 7)] * (1.0f / 1024.0f);
        }
        __syncthreads();
    } else {
        const int w = tid >> 5, lane = tid & 31;
        const int bl = w / 10;
        const int r  = w % 10;
        const int k0 = (r >> 1) * 4;
        const int a0 = (r & 1) * 4;

        unsigned long long acc[4][4];
        #pragma unroll
        for (int kk = 0; kk < 4; kk++)
            #pragma unroll
            for (int aa = 0; aa < 4; aa++) acc[kk][aa] = 0ull;

        #pragma unroll 2
        for (int j = 0; j < 8; j++) {
            const int m = j * 128 + lane * 4;
            ulonglong2 ck0 = *(const ulonglong2*)(sm + CS + (k0 + 0) * MUL + m);
            ulonglong2 ck1 = *(const ulonglong2*)(sm + CS + (k0 + 1) * MUL + m);
            ulonglong2 ck2 = *(const ulonglong2*)(sm + CS + (k0 + 2) * MUL + m);
            ulonglong2 ck3 = *(const ulonglong2*)(sm + CS + (k0 + 3) * MUL + m);
            #pragma unroll
            for (int aa = 0; aa < 4; aa++) {
                ulonglong2 xv = *(const ulonglong2*)(sm + XS + (bl * 8 + a0 + aa) * PLF + m);
                FMA2(acc[0][aa], ck0.x, xv.x); FMA2(acc[0][aa], ck0.y, xv.y);
                FMA2(acc[1][aa], ck1.x, xv.x); FMA2(acc[1][aa], ck1.y, xv.y);
                FMA2(acc[2][aa], ck2.x, xv.x); FMA2(acc[2][aa], ck2.y, xv.y);
                FMA2(acc[3][aa], ck3.x, xv.x); FMA2(acc[3][aa], ck3.y, xv.y);
            }
        }
        #pragma unroll
        for (int kk = 0; kk < 4; kk++) {
            #pragma unroll
            for (int aa = 0; aa < 4; aa++) {
                float v = lo_f(acc[kk][aa]) + hi_f(acc[kk][aa]);
                WARP_RED_SUM(v);
                if (lane == 0) sm[YS + bl * 160 + (k0 + kk) * 8 + a0 + aa] = v;
            }
        }
        __syncthreads();
    }

    // ---- tail: s = W y, squash (class-sum per reference), v ----
    const int bl = tid / 320, r = tid % 320;
    const int k = r >> 4, o = r & 15;
    {
        const float* wk = W + r * 8;
        const float* yk = sm + YS + bl * 160 + k * 8;
        float s = 0.f;
        #pragma unroll
        for (int a = 0; a < 8; a++) s += wk[a] * yk[a];
        sm[SV + bl * 320 + r] = s;
        __syncthreads();

        if (tid < 32) {
            int bb = tid >> 4, oo = tid & 15;
            float msq = 0.f;
            #pragma unroll
            for (int kk = 0; kk < NK; kk++) {
                float t = sm[SV + bb * 320 + kk * 16 + oo];
                msq += t * t;
            }
            sm[CQ + bb * 16 + oo] = msq / ((1.f + msq) * sqrtf(msq));
        }
        __syncthreads();

        float v = sm[CQ + bl * 16 + o] * s;
        if (final_iter) {
            out[(size_t)(b0 + bl) * 320 + r] = v;     // coalesced; done
            return;
        }
        sm[SV + bl * 320 + r] = v;
        __syncthreads();

        // wv[bl][k][a] = sum_o W[k,o,a] * v[bl,k,o]  -> smem
        if (tid < 320) {
            int bb = tid / 160, rr = tid % 160;
            int kk = rr >> 3, aa = rr & 7;
            float acc = 0.f;
            #pragma unroll
            for (int oo = 0; oo < 16; oo++)
                acc += W[(kk * 16 + oo) * 8 + aa] * sm[SV + bb * 320 + kk * 16 + oo];
            sm[WVm + bb * 160 + rr] = acc;
        }
    }
    __syncthreads();

    // ---- agree phase: agr[m][k] = sum_{bl,a} x[bl,a,m]*wv[bl,k,a] ----
    {
        float* agr = sm + CS;                 // overlay on c region [1024][20]
        const int mqi = tid / NK;             // 0..31
        const int k2  = tid % NK;

        unsigned long long wvd[16];
        #pragma unroll
        for (int i = 0; i < 16; i++) {
            unsigned u = __float_as_uint(sm[WVm + (i >> 3) * 160 + k2 * 8 + (i & 7)]);
            wvd[i] = (unsigned long long)u | ((unsigned long long)u << 32);
        }

        #pragma unroll 2
        for (int rr = 0; rr < 8; rr++) {
            const int m0 = rr * 128 + mqi * 4;
            unsigned long long a01 = 0ull, a23 = 0ull;
            #pragma unroll
            for (int i = 0; i < 16; i++) {
                ulonglong2 xv = *(const ulonglong2*)(sm + XS + i * PLF + m0);
                FMA2(a01, xv.x, wvd[i]);
                FMA2(a23, xv.y, wvd[i]);
            }
            float* d = agr + m0 * NK + k2;
            d[0]      = lo_f(a01);
            d[NK]     = hi_f(a01);
            d[2 * NK] = lo_f(a23);
            d[3 * NK] = hi_f(a23);
        }
        __syncthreads();

        // flush transposed [k][m] with 1/256 scale, coalesced float4
        float* gp = g_bpart + (size_t)blockIdx.x * (NK * MUL);
        #pragma unroll
        for (int i = 0; i < 8; i++) {
            int q  = tid + i * F_THREADS;     // 0..5119
            int kk = q >> 8, mq = q & 255;
            float4 v;
            v.x = agr[(mq * 4 + 0) * NK + kk] * (1.0f / 256.0f);
            v.y = agr[(mq * 4 + 1) * NK + kk] * (1.0f / 256.0f);
            v.z = agr[(mq * 4 + 2) * NK + kk] * (1.0f / 256.0f);
            v.w = agr[(mq * 4 + 3) * NK + kk] * (1.0f / 256.0f);
            *(float4*)(gp + kk * MUL + mq * 4) = v;
        }
    }
}

// ---------------------------------------------------------------------------
// Softmax kernel: 20 blocks x 1024 threads. Combine 128 slices -> b
// (optionally accumulate), exp, row-sum, normalize -> c.
// No max subtraction (inputs bounded; fp32-safe; validated R12).
// ---------------------------------------------------------------------------
__global__ void __launch_bounds__(1024)
softmax_kernel(int accum)
{
    const int k = blockIdx.x;
    const int t = threadIdx.x;
    const int lane = t & 31, wp = t >> 5;
    __shared__ float red[32];
    __shared__ float bc;

    float b = accum ? g_b[k * MUL + t] : 0.f;
    #pragma unroll 8
    for (int p = 0; p < 128; p++)
        b += g_bpart[(size_t)p * (NK * MUL) + k * MUL + t];
    g_b[k * MUL + t] = b;

    float e = expf(b);
    float s = e;
    #pragma unroll
    for (int off = 16; off; off >>= 1)
        s += __shfl_xor_sync(0xffffffffu, s, off);
    if (lane == 0) red[wp] = s;
    __syncthreads();
    if (t < 32) {
        float ss = red[t];
        #pragma unroll
        for (int off = 16; off; off >>= 1)
            ss += __shfl_xor_sync(0xffffffffu, ss, off);
        if (t == 0) bc = ss;
    }
    __syncthreads();

    g_c[k * MUL + t] = e * (1.0f / bc);
}

// ---------------------------------------------------------------------------
extern "C" void kernel_launch(void* const* d_in, const int* in_sizes, int n_in,
                              void* d_out, int out_size)
{
    const float* x = (const float*)d_in[0];   // [256][1024][8] flat view
    const float* W = (const float*)d_in[1];   // [20][16][8]
    float* out = (float*)d_out;               // [256][20][16][1]

    const int F_SMEM = F_FLOATS * (int)sizeof(float);   // 153.5 KB
    cudaFuncSetAttribute(fused_kernel,
                         cudaFuncAttributeMaxDynamicSharedMemorySize, F_SMEM);

    // iteration 0 (uniform c): y0 + tail + wv + agree, then softmax -> c1
    fused_kernel<<<B_TOT / 2, F_THREADS, F_SMEM>>>(x, W, out, 1, 0);
    softmax_kernel<<<NK, 1024>>>(0);

    // iteration 1: y1 + tail + wv + agree, then softmax -> c2
    fused_kernel<<<B_TOT / 2, F_THREADS, F_SMEM>>>(x, W, out, 0, 0);
    softmax_kernel<<<NK, 1024>>>(1);

    // iteration 2 (final): y2 + tail -> output
    fused_kernel<<<B_TOT / 2, F_THREADS, F_SMEM>>>(x, W, out, 0, 1);
}

// round 17
// speedup vs baseline: 1.2158x; 1.0368x over previous
#include <cuda_runtime.h>
#include <math.h>

// Problem constants
#define B_TOT 256
#define AIN   8
#define MUL   1024
#define NK    20
#define NO    16
#define PLF   1036          // plane stride (floats)

// Persistent scratch (device globals; allocation-free)
__device__ __align__(16) float g_c[NK * MUL];
__device__ __align__(16) float g_b[NK * MUL];
__device__ __align__(16) float g_bpart[128 * NK * MUL];   // per-F-block agree slices

// Packed f32x2 FMA
#define FMA2(acc, a, b) \
    asm("fma.rn.f32x2 %0, %1, %2, %0;" : "+l"(acc) : "l"(a), "l"(b))

__device__ __forceinline__ float lo_f(unsigned long long u) {
    return __uint_as_float((unsigned)(u & 0xffffffffu));
}
__device__ __forceinline__ float hi_f(unsigned long long u) {
    return __uint_as_float((unsigned)(u >> 32));
}

#define WARP_RED_SUM(v)                                   \
  do {                                                    \
    v += __shfl_xor_sync(0xffffffffu, v, 16);             \
    v += __shfl_xor_sync(0xffffffffu, v, 8);              \
    v += __shfl_xor_sync(0xffffffffu, v, 4);              \
    v += __shfl_xor_sync(0xffffffffu, v, 2);              \
    v += __shfl_xor_sync(0xffffffffu, v, 1);              \
  } while (0)

// F smem layout (floats); total 38384 = 153.5 KB dynamic, 1 block/SM
#define XS   0          // x planes [16][PLF]        16576
#define CS   16576      // c [20][1024]; agr overlay [1024][20]  20480
#define YS   37056      // ysm [2][20][8]              320
#define SV   37376      // svm [2][320]                640
#define CQ   38016      // cqm [2][16]                  32
#define WVm  38048      // wvm [2][160]                320
#define RED  38368      // red [16]                     16
#define F_FLOATS 38384
#define F_THREADS 640

// ---------------------------------------------------------------------------
// Fused kernel (R16, proven): block = batch-pair (128 blocks).
//   stage x planes (+c if !uniform) -> y -> tail(s,squash,v) ->
//   final: write out | else: wv (smem) -> agree partials -> g_bpart[block].
// ---------------------------------------------------------------------------
__global__ void __launch_bounds__(F_THREADS, 1)
fused_kernel(const float* __restrict__ x, const float* __restrict__ W,
             float* __restrict__ out, int uniform_c, int final_iter)
{
    extern __shared__ float sm[];
    const int tid = threadIdx.x;
    const int b0  = blockIdx.x * 2;

    // ---- stage x transposed to planes ----
    {
        const float4* xsrc = (const float4*)(x + (size_t)b0 * 8192);
        #pragma unroll 2
        for (int i = tid; i < 4096; i += F_THREADS) {
            int bl = i >> 11, f = i & 2047;
            int m = f >> 1, half = f & 1;
            float4 v = xsrc[i];
            float* base = sm + XS + (bl * 8 + half * 4) * PLF + m;
            base[0 * PLF] = v.x; base[1 * PLF] = v.y;
            base[2 * PLF] = v.z; base[3 * PLF] = v.w;
        }
    }
    // ---- stage c (skipped on uniform iteration 0) ----
    if (!uniform_c) {
        const float4* csrc = (const float4*)g_c;
        float4* cdst = (float4*)(sm + CS);
        #pragma unroll
        for (int i = 0; i < 8; i++) cdst[tid + i * F_THREADS] = csrc[tid + i * F_THREADS];
    }
    __syncthreads();

    // ---- y phase ----
    if (uniform_c) {
        const int w = tid >> 5, lane = tid & 31;
        if (w < 16) {
            const float* pl = sm + XS + w * PLF;
            float s = 0.f;
            #pragma unroll 8
            for (int t = 0; t < 32; t++) s += pl[t * 32 + lane];
            WARP_RED_SUM(s);
            if (lane == 0) sm[RED + w] = s;
        }
        __syncthreads();
        if (tid < 320) {
            int bl = tid / 160, rr = tid % 160;
            sm[YS + bl * 160 + rr] = sm[RED + bl * 8 + (rr & 7)] * (1.0f / 1024.0f);
        }
        __syncthreads();
    } else {
        const int w = tid >> 5, lane = tid & 31;
        const int bl = w / 10;
        const int r  = w % 10;
        const int k0 = (r >> 1) * 4;
        const int a0 = (r & 1) * 4;

        unsigned long long acc[4][4];
        #pragma unroll
        for (int kk = 0; kk < 4; kk++)
            #pragma unroll
            for (int aa = 0; aa < 4; aa++) acc[kk][aa] = 0ull;

        #pragma unroll 2
        for (int j = 0; j < 8; j++) {
            const int m = j * 128 + lane * 4;
            ulonglong2 ck0 = *(const ulonglong2*)(sm + CS + (k0 + 0) * MUL + m);
            ulonglong2 ck1 = *(const ulonglong2*)(sm + CS + (k0 + 1) * MUL + m);
            ulonglong2 ck2 = *(const ulonglong2*)(sm + CS + (k0 + 2) * MUL + m);
            ulonglong2 ck3 = *(const ulonglong2*)(sm + CS + (k0 + 3) * MUL + m);
            #pragma unroll
            for (int aa = 0; aa < 4; aa++) {
                ulonglong2 xv = *(const ulonglong2*)(sm + XS + (bl * 8 + a0 + aa) * PLF + m);
                FMA2(acc[0][aa], ck0.x, xv.x); FMA2(acc[0][aa], ck0.y, xv.y);
                FMA2(acc[1][aa], ck1.x, xv.x); FMA2(acc[1][aa], ck1.y, xv.y);
                FMA2(acc[2][aa], ck2.x, xv.x); FMA2(acc[2][aa], ck2.y, xv.y);
                FMA2(acc[3][aa], ck3.x, xv.x); FMA2(acc[3][aa], ck3.y, xv.y);
            }
        }
        #pragma unroll
        for (int kk = 0; kk < 4; kk++) {
            #pragma unroll
            for (int aa = 0; aa < 4; aa++) {
                float v = lo_f(acc[kk][aa]) + hi_f(acc[kk][aa]);
                WARP_RED_SUM(v);
                if (lane == 0) sm[YS + bl * 160 + (k0 + kk) * 8 + a0 + aa] = v;
            }
        }
        __syncthreads();
    }

    // ---- tail: s = W y, squash (class-sum per reference), v ----
    const int bl = tid / 320, r = tid % 320;
    const int k = r >> 4, o = r & 15;
    {
        const float* wk = W + r * 8;
        const float* yk = sm + YS + bl * 160 + k * 8;
        float s = 0.f;
        #pragma unroll
        for (int a = 0; a < 8; a++) s += wk[a] * yk[a];
        sm[SV + bl * 320 + r] = s;
        __syncthreads();

        if (tid < 32) {
            int bb = tid >> 4, oo = tid & 15;
            float msq = 0.f;
            #pragma unroll
            for (int kk = 0; kk < NK; kk++) {
                float t = sm[SV + bb * 320 + kk * 16 + oo];
                msq += t * t;
            }
            sm[CQ + bb * 16 + oo] = msq / ((1.f + msq) * sqrtf(msq));
        }
        __syncthreads();

        float v = sm[CQ + bl * 16 + o] * s;
        if (final_iter) {
            out[(size_t)(b0 + bl) * 320 + r] = v;     // coalesced; done
            return;
        }
        sm[SV + bl * 320 + r] = v;
        __syncthreads();

        // wv[bl][k][a] = sum_o W[k,o,a] * v[bl,k,o]  -> smem
        if (tid < 320) {
            int bb = tid / 160, rr = tid % 160;
            int kk = rr >> 3, aa = rr & 7;
            float acc = 0.f;
            #pragma unroll
            for (int oo = 0; oo < 16; oo++)
                acc += W[(kk * 16 + oo) * 8 + aa] * sm[SV + bb * 320 + kk * 16 + oo];
            sm[WVm + bb * 160 + rr] = acc;
        }
    }
    __syncthreads();

    // ---- agree phase: agr[m][k] = sum_{bl,a} x[bl,a,m]*wv[bl,k,a] ----
    {
        float* agr = sm + CS;                 // overlay on c region [1024][20]
        const int mqi = tid / NK;             // 0..31
        const int k2  = tid % NK;

        unsigned long long wvd[16];
        #pragma unroll
        for (int i = 0; i < 16; i++) {
            unsigned u = __float_as_uint(sm[WVm + (i >> 3) * 160 + k2 * 8 + (i & 7)]);
            wvd[i] = (unsigned long long)u | ((unsigned long long)u << 32);
        }

        #pragma unroll 2
        for (int rr = 0; rr < 8; rr++) {
            const int m0 = rr * 128 + mqi * 4;
            unsigned long long a01 = 0ull, a23 = 0ull;
            #pragma unroll
            for (int i = 0; i < 16; i++) {
                ulonglong2 xv = *(const ulonglong2*)(sm + XS + i * PLF + m0);
                FMA2(a01, xv.x, wvd[i]);
                FMA2(a23, xv.y, wvd[i]);
            }
            float* d = agr + m0 * NK + k2;
            d[0]      = lo_f(a01);
            d[NK]     = hi_f(a01);
            d[2 * NK] = lo_f(a23);
            d[3 * NK] = hi_f(a23);
        }
        __syncthreads();

        // flush transposed [k][m] with 1/256 scale, coalesced float4
        float* gp = g_bpart + (size_t)blockIdx.x * (NK * MUL);
        #pragma unroll
        for (int i = 0; i < 8; i++) {
            int q  = tid + i * F_THREADS;     // 0..5119
            int kk = q >> 8, mq = q & 255;
            float4 v;
            v.x = agr[(mq * 4 + 0) * NK + kk] * (1.0f / 256.0f);
            v.y = agr[(mq * 4 + 1) * NK + kk] * (1.0f / 256.0f);
            v.z = agr[(mq * 4 + 2) * NK + kk] * (1.0f / 256.0f);
            v.w = agr[(mq * 4 + 3) * NK + kk] * (1.0f / 256.0f);
            *(float4*)(gp + kk * MUL + mq * 4) = v;
        }
    }
}

// ---------------------------------------------------------------------------
// Combine kernel: grid (20, 4) x 256 threads. Each thread owns one (k,m) and
// sums all 128 slices (L2-resident, coalesced, deep MLP). Accum into g_b.
// ---------------------------------------------------------------------------
__global__ void __launch_bounds__(256)
combine_kernel(int accum)
{
    const int k = blockIdx.x;
    const int m = blockIdx.y * 256 + threadIdx.x;
    const int idx = k * MUL + m;

    float b = accum ? g_b[idx] : 0.f;
    #pragma unroll 16
    for (int p = 0; p < 128; p++)
        b += g_bpart[(size_t)p * (NK * MUL) + idx];
    g_b[idx] = b;
}

// ---------------------------------------------------------------------------
// Softmax kernel: 20 blocks x 1024 threads, reads combined g_b (80 KB).
// No max subtraction (inputs bounded; fp32-safe; validated R12).
// ---------------------------------------------------------------------------
__global__ void __launch_bounds__(1024)
softmax_kernel()
{
    const int k = blockIdx.x;
    const int t = threadIdx.x;
    const int lane = t & 31, wp = t >> 5;
    __shared__ float red[32];
    __shared__ float bc;

    float e = expf(g_b[k * MUL + t]);
    float s = e;
    #pragma unroll
    for (int off = 16; off; off >>= 1)
        s += __shfl_xor_sync(0xffffffffu, s, off);
    if (lane == 0) red[wp] = s;
    __syncthreads();
    if (t < 32) {
        float ss = red[t];
        #pragma unroll
        for (int off = 16; off; off >>= 1)
            ss += __shfl_xor_sync(0xffffffffu, ss, off);
        if (t == 0) bc = ss;
    }
    __syncthreads();

    g_c[k * MUL + t] = e * (1.0f / bc);
}

// ---------------------------------------------------------------------------
extern "C" void kernel_launch(void* const* d_in, const int* in_sizes, int n_in,
                              void* d_out, int out_size)
{
    const float* x = (const float*)d_in[0];   // [256][1024][8] flat view
    const float* W = (const float*)d_in[1];   // [20][16][8]
    float* out = (float*)d_out;               // [256][20][16][1]

    const int F_SMEM = F_FLOATS * (int)sizeof(float);   // 153.5 KB
    cudaFuncSetAttribute(fused_kernel,
                         cudaFuncAttributeMaxDynamicSharedMemorySize, F_SMEM);

    dim3 cgrid(NK, 4);

    // iteration 0 (uniform c): y0 + tail + wv + agree; combine; softmax -> c1
    fused_kernel<<<B_TOT / 2, F_THREADS, F_SMEM>>>(x, W, out, 1, 0);
    combine_kernel<<<cgrid, 256>>>(0);
    softmax_kernel<<<NK, 1024>>>();

    // iteration 1: y1 + tail + wv + agree; combine; softmax -> c2
    fused_kernel<<<B_TOT / 2, F_THREADS, F_SMEM>>>(x, W, out, 0, 0);
    combine_kernel<<<cgrid, 256>>>(1);
    softmax_kernel<<<NK, 1024>>>();

    // iteration 2 (final): y2 + tail -> output
    fused_kernel<<<B_TOT / 2, F_THREADS, F_SMEM>>>(x, W, out, 0, 1);
}